// round 4
// baseline (speedup 1.0000x reference)
#include <cuda_runtime.h>
#include <cstdint>

#define B_SZ   8192
#define K_DIM  1024
#define V_N    2
#define BT     64      // batch rows per CTA
#define PP     64      // panel width (columns per step)
#define KC     32      // k-chunk for GEMM tiles
#define NTH    128     // threads per CTA
#define NPAN   (K_DIM / PP)

// -------- packed f32x2 helpers (B300 FFMA2 path, PTX-only) --------
__device__ __forceinline__ unsigned long long pack2(float x) {
    unsigned long long r;
    unsigned int u = __float_as_uint(x);
    asm("mov.b64 %0, {%1, %1};" : "=l"(r) : "r"(u));
    return r;
}
__device__ __forceinline__ unsigned long long ffma2(unsigned long long a,
                                                    unsigned long long b,
                                                    unsigned long long c) {
    unsigned long long d;
    asm("fma.rn.f32x2 %0, %1, %2, %3;" : "=l"(d) : "l"(a), "l"(b), "l"(c));
    return d;
}

__global__ void __launch_bounds__(NTH, 1)
scm_kernel(const float* __restrict__ z,
           const int*   __restrict__ tgt,
           const int*   __restrict__ vari,
           const float* __restrict__ A,
           const float* __restrict__ means,
           const float* __restrict__ logsc,
           float*       __restrict__ out)
{
    // k-major tiles for vectorized fragment loads
    __shared__ __align__(16) float u_s[KC][BT + 4];     // u_s[k][b]
    __shared__ __align__(16) float a_s[KC][PP + 4];     // a_s[k][jj]
    __shared__ __align__(16) float diag_s[PP][PP + 4];  // diag_s[i][jj] = A[j0+jj][j0+i]
    __shared__ __align__(16) float up_s[BT][PP + 4];    // panel staging

    const int tid = threadIdx.x;
    const int b0  = blockIdx.x * BT;
    const int bg  = tid >> 3;   // 0..15 -> rows 4*bg..4*bg+3
    const int jg  = tid & 7;    // 0..7  -> cols 8*jg..8*jg+7

    // ---- per-sample intervention scalar (threads 0..63, one sample each) ----
    int   t_abs = -(1 << 30);
    float vint  = 0.0f;
    if (tid < BT) {
        const int b = b0 + tid;
        const int t = tgt[b];
        if (t >= 0) {
            const int v   = vari[b];
            const float m = means[t * V_N + v];
            const float s = expf(logsc[t * V_N + v]);
            vint  = fmaf(s, z[(size_t)b * K_DIM + t], m);
            t_abs = t;
        }
    }

    for (int p = 0; p < NPAN; ++p) {
        const int j0 = p * PP;

        // ---- load diagonal block (transposed): diag_s[i][jj] = A[(j0+jj)*K + j0+i]
        {
            const int jj = tid & 63;
            const int ih = (tid >> 6) * 32;   // 0 or 32
            const float* src = A + (size_t)(j0 + jj) * K_DIM + j0 + ih;
            #pragma unroll
            for (int q = 0; q < 8; ++q) {
                const float4 r = *(const float4*)(src + 4 * q);
                diag_s[ih + 4*q + 0][jj] = r.x;
                diag_s[ih + 4*q + 1][jj] = r.y;
                diag_s[ih + 4*q + 2][jj] = r.z;
                diag_s[ih + 4*q + 3][jj] = r.w;
            }
        }

        // ---- GEMM update: acc[b][jj] = sum_{k<j0} u[b][k] * A[j0+jj][k] ----
        unsigned long long acc[4][4];   // 4 b-rows x 4 jj-pairs (f32x2)
        #pragma unroll
        for (int i = 0; i < 4; ++i)
            #pragma unroll
            for (int j = 0; j < 4; ++j) acc[i][j] = 0ULL;

        const int nkb = 2 * p;   // j0 / KC
        if (nkb > 0) {
            float4 ru[4], ra[4];
            // preload kb = 0 (rows: u from our finished output region; A rows j0+jj)
            #pragma unroll
            for (int q = 0; q < 4; ++q) {
                const int f = tid + NTH * q;
                const int row = f >> 3, c = f & 7;
                ru[q] = *(const float4*)(out + (size_t)(b0 + row) * K_DIM + 4 * c);
                ra[q] = *(const float4*)(A   + (size_t)(j0 + row) * K_DIM + 4 * c);
            }
            #pragma unroll
            for (int q = 0; q < 4; ++q) {
                const int f = tid + NTH * q;
                const int row = f >> 3, c = f & 7;
                u_s[4*c+0][row] = ru[q].x; u_s[4*c+1][row] = ru[q].y;
                u_s[4*c+2][row] = ru[q].z; u_s[4*c+3][row] = ru[q].w;
                a_s[4*c+0][row] = ra[q].x; a_s[4*c+1][row] = ra[q].y;
                a_s[4*c+2][row] = ra[q].z; a_s[4*c+3][row] = ra[q].w;
            }
            __syncthreads();

            for (int kb = 0; kb < nkb; ++kb) {
                const bool more = (kb + 1 < nkb);
                if (more) {
                    #pragma unroll
                    for (int q = 0; q < 4; ++q) {
                        const int f = tid + NTH * q;
                        const int row = f >> 3, c = f & 7;
                        ru[q] = *(const float4*)(out + (size_t)(b0 + row) * K_DIM + (kb + 1) * KC + 4 * c);
                        ra[q] = *(const float4*)(A   + (size_t)(j0 + row) * K_DIM + (kb + 1) * KC + 4 * c);
                    }
                }
                #pragma unroll 4
                for (int k = 0; k < KC; ++k) {
                    const float4 av = *(const float4*)&u_s[k][4 * bg];
                    const ulonglong2 b01 = *(const ulonglong2*)&a_s[k][8 * jg];
                    const ulonglong2 b23 = *(const ulonglong2*)&a_s[k][8 * jg + 4];
                    unsigned long long bb2[4];
                    bb2[0] = b01.x; bb2[1] = b01.y; bb2[2] = b23.x; bb2[3] = b23.y;
                    float aa[4];
                    aa[0] = av.x; aa[1] = av.y; aa[2] = av.z; aa[3] = av.w;
                    #pragma unroll
                    for (int i2 = 0; i2 < 4; ++i2) {
                        const unsigned long long ad = pack2(aa[i2]);
                        #pragma unroll
                        for (int j2 = 0; j2 < 4; ++j2)
                            acc[i2][j2] = ffma2(ad, bb2[j2], acc[i2][j2]);
                    }
                }
                __syncthreads();
                if (more) {
                    #pragma unroll
                    for (int q = 0; q < 4; ++q) {
                        const int f = tid + NTH * q;
                        const int row = f >> 3, c = f & 7;
                        u_s[4*c+0][row] = ru[q].x; u_s[4*c+1][row] = ru[q].y;
                        u_s[4*c+2][row] = ru[q].z; u_s[4*c+3][row] = ru[q].w;
                        a_s[4*c+0][row] = ra[q].x; a_s[4*c+1][row] = ra[q].y;
                        a_s[4*c+2][row] = ra[q].z; a_s[4*c+3][row] = ra[q].w;
                    }
                    __syncthreads();
                }
            }
        }

        // ---- stage acc into up_s (f32x2 pairs land on consecutive floats) ----
        #pragma unroll
        for (int i2 = 0; i2 < 4; ++i2)
            #pragma unroll
            for (int j2 = 0; j2 < 4; ++j2)
                *(unsigned long long*)&up_s[4 * bg + i2][8 * jg + 2 * j2] = acc[i2][j2];
        __syncthreads();   // also orders diag_s writes before micro-solve

        // ---- in-panel sequential micro-solve: thread b owns one sample ----
        if (tid < BT) {
            float ul[PP];
            const float* zp = z + (size_t)(b0 + tid) * K_DIM + j0;
            #pragma unroll
            for (int q = 0; q < 16; ++q) {
                const float4 zq = *(const float4*)(zp + 4 * q);
                const float4 aq = *(const float4*)&up_s[tid][4 * q];
                ul[4*q+0] = aq.x + zq.x;
                ul[4*q+1] = aq.y + zq.y;
                ul[4*q+2] = aq.z + zq.z;
                ul[4*q+3] = aq.w + zq.w;
            }
            const int jrel = t_abs - j0;
            // column sweep with rank-1 updates: no long FMA dependency chains
            #pragma unroll
            for (int i = 0; i < PP; ++i) {
                float val = ul[i];
                if (jrel == i) val = vint;
                ul[i] = val;
                #pragma unroll
                for (int jj = i + 1; jj < PP; ++jj)
                    ul[jj] = fmaf(diag_s[i][jj], val, ul[jj]);
            }
            #pragma unroll
            for (int q = 0; q < 16; ++q) {
                float4 v;
                v.x = ul[4*q+0]; v.y = ul[4*q+1]; v.z = ul[4*q+2]; v.w = ul[4*q+3];
                *(float4*)&up_s[tid][4 * q] = v;
            }
        }
        __syncthreads();

        // ---- coalesced panel writeout (out also serves as u-scratch) ----
        {
            const int r0 = tid >> 4;          // 0..7
            const int c0 = (tid & 15) * 4;    // 0..60
            #pragma unroll
            for (int pass = 0; pass < 8; ++pass) {
                const int row = pass * 8 + r0;
                const float4 v = *(const float4*)&up_s[row][c0];
                *(float4*)(out + (size_t)(b0 + row) * K_DIM + j0 + c0) = v;
            }
        }
        __syncthreads();   // global writes visible to next panel's GEMM reads
    }
}

extern "C" void kernel_launch(void* const* d_in, const int* in_sizes, int n_in,
                              void* d_out, int out_size) {
    const float* z     = (const float*)d_in[0];
    const int*   tgt   = (const int*)  d_in[1];
    const int*   vari  = (const int*)  d_in[2];
    const float* A     = (const float*)d_in[3];
    const float* means = (const float*)d_in[4];
    const float* logsc = (const float*)d_in[5];
    float* out = (float*)d_out;
    (void)in_sizes; (void)n_in; (void)out_size;

    scm_kernel<<<B_SZ / BT, NTH>>>(z, tgt, vari, A, means, logsc, out);
}

// round 5
// speedup vs baseline: 1.1905x; 1.1905x over previous
#include <cuda_runtime.h>
#include <cstdint>

#define B_SZ   8192
#define K_DIM  1024
#define V_N    2
#define BT     64      // batch rows per CTA
#define PP     64      // panel width
#define KC     32      // k-chunk
#define NTH    256     // threads per CTA (8 warps = 2/SMSP)
#define NPAN   (K_DIM / PP)
#define UR     (2*BT + 4)   // u_dup row stride (floats) = 132, 16B-aligned rows
#define AR     (PP + 4)     // 68, 16B-aligned rows

// -------- packed f32x2 helpers (B300 FFMA2 path, PTX-only) --------
__device__ __forceinline__ unsigned long long pack2(float x) {
    unsigned long long r;
    unsigned int u = __float_as_uint(x);
    asm("mov.b64 %0, {%1, %1};" : "=l"(r) : "r"(u));
    return r;
}
__device__ __forceinline__ unsigned long long ffma2(unsigned long long a,
                                                    unsigned long long b,
                                                    unsigned long long c) {
    unsigned long long d;
    asm("fma.rn.f32x2 %0, %1, %2, %3;" : "=l"(d) : "l"(a), "l"(b), "l"(c));
    return d;
}

// GEMM-phase and solve-phase smem alias (phases separated by syncs)
union SMem {
    struct {
        float u_dup[KC][UR];   // duplicated pairs: u_dup[k][2b..2b+1] = u[b]
        float a_s[KC][AR];     // a_s[k][jj] = A[j0+jj][kb*KC + k]
    } g;
    struct {
        float diag[PP][AR];    // diag[i][jj] = A[j0+jj][j0+i], zeroed for jj<=i
        float up[BT][AR];      // panel values
    } m;
};

__global__ void __launch_bounds__(NTH, 1)
scm_kernel(const float* __restrict__ z,
           const int*   __restrict__ tgt,
           const int*   __restrict__ vari,
           const float* __restrict__ A,
           const float* __restrict__ means,
           const float* __restrict__ logsc,
           float*       __restrict__ out)
{
    __shared__ __align__(16) SMem sm;

    const int tid = threadIdx.x;
    const int b0  = blockIdx.x * BT;
    const int bg  = tid >> 4;   // 0..15 -> rows 4*bg..4*bg+3
    const int jg  = tid & 15;   // 0..15 -> cols 4*jg..4*jg+3

    // ---- per-sample intervention scalar (threads 0..63) ----
    int   t_abs = -(1 << 30);
    float vint  = 0.0f;
    if (tid < BT) {
        const int b = b0 + tid;
        const int t = tgt[b];
        if (t >= 0) {
            const int v   = vari[b];
            const float m = means[t * V_N + v];
            const float s = expf(logsc[t * V_N + v]);
            vint  = fmaf(s, z[(size_t)b * K_DIM + t], m);
            t_abs = t;
        }
    }

    for (int p = 0; p < NPAN; ++p) {
        const int j0 = p * PP;

        // ================= GEMM: acc[b][jj] = sum_{k<j0} u[b][k]*A[j0+jj][k] ==
        unsigned long long acc[4][2];
        #pragma unroll
        for (int i = 0; i < 4; ++i) { acc[i][0] = 0ULL; acc[i][1] = 0ULL; }

        const int nkb = 2 * p;
        if (nkb > 0) {
            float4 ru[2], ra[2];
            // prefetch chunk 0
            #pragma unroll
            for (int q = 0; q < 2; ++q) {
                const int f = tid + NTH * q;
                const int r = f >> 3, c = f & 7;
                ru[q] = *(const float4*)(out + (size_t)(b0 + r) * K_DIM + 4 * c);
                ra[q] = *(const float4*)(A   + (size_t)(j0 + r) * K_DIM + 4 * c);
            }
            // store chunk 0
            #pragma unroll
            for (int q = 0; q < 2; ++q) {
                const int f = tid + NTH * q;
                const int r = f >> 3, c = f & 7;
                const float uv[4] = {ru[q].x, ru[q].y, ru[q].z, ru[q].w};
                const float av[4] = {ra[q].x, ra[q].y, ra[q].z, ra[q].w};
                #pragma unroll
                for (int j = 0; j < 4; ++j) {
                    *(unsigned long long*)&sm.g.u_dup[4*c + j][2*r] = pack2(uv[j]);
                    sm.g.a_s[4*c + j][r] = av[j];
                }
            }
            __syncthreads();

            for (int kb = 0; kb < nkb; ++kb) {
                const bool more = (kb + 1 < nkb);
                if (more) {
                    #pragma unroll
                    for (int q = 0; q < 2; ++q) {
                        const int f = tid + NTH * q;
                        const int r = f >> 3, c = f & 7;
                        ru[q] = *(const float4*)(out + (size_t)(b0 + r) * K_DIM + (kb + 1) * KC + 4 * c);
                        ra[q] = *(const float4*)(A   + (size_t)(j0 + r) * K_DIM + (kb + 1) * KC + 4 * c);
                    }
                }
                #pragma unroll 8
                for (int k = 0; k < KC; ++k) {
                    const ulonglong2 u01 = *(const ulonglong2*)&sm.g.u_dup[k][8 * bg];
                    const ulonglong2 u23 = *(const ulonglong2*)&sm.g.u_dup[k][8 * bg + 4];
                    const ulonglong2 bp  = *(const ulonglong2*)&sm.g.a_s[k][4 * jg];
                    acc[0][0] = ffma2(u01.x, bp.x, acc[0][0]);
                    acc[0][1] = ffma2(u01.x, bp.y, acc[0][1]);
                    acc[1][0] = ffma2(u01.y, bp.x, acc[1][0]);
                    acc[1][1] = ffma2(u01.y, bp.y, acc[1][1]);
                    acc[2][0] = ffma2(u23.x, bp.x, acc[2][0]);
                    acc[2][1] = ffma2(u23.x, bp.y, acc[2][1]);
                    acc[3][0] = ffma2(u23.y, bp.x, acc[3][0]);
                    acc[3][1] = ffma2(u23.y, bp.y, acc[3][1]);
                }
                __syncthreads();
                if (more) {
                    #pragma unroll
                    for (int q = 0; q < 2; ++q) {
                        const int f = tid + NTH * q;
                        const int r = f >> 3, c = f & 7;
                        const float uv[4] = {ru[q].x, ru[q].y, ru[q].z, ru[q].w};
                        const float av[4] = {ra[q].x, ra[q].y, ra[q].z, ra[q].w};
                        #pragma unroll
                        for (int j = 0; j < 4; ++j) {
                            *(unsigned long long*)&sm.g.u_dup[4*c + j][2*r] = pack2(uv[j]);
                            sm.g.a_s[4*c + j][r] = av[j];
                        }
                    }
                    __syncthreads();
                }
            }
        }

        // ========== switch to solve-phase smem (aliases GEMM tiles) ==========
        // write acc -> up
        #pragma unroll
        for (int i2 = 0; i2 < 4; ++i2) {
            *(unsigned long long*)&sm.m.up[4*bg + i2][4*jg]     = acc[i2][0];
            *(unsigned long long*)&sm.m.up[4*bg + i2][4*jg + 2] = acc[i2][1];
        }
        // load diagonal block, transposed + strictly-lower masked:
        // diag[i][jj] = (i < jj) ? A[(j0+jj)*K + j0 + i] : 0
        {
            const int jj  = tid & 63;
            const int ig0 = (tid >> 6) * 16;   // 4 groups x 16 i-values
            const float* src = A + (size_t)(j0 + jj) * K_DIM + j0 + ig0;
            #pragma unroll
            for (int q = 0; q < 4; ++q) {
                const float4 r = *(const float4*)(src + 4 * q);
                const int i = ig0 + 4 * q;
                sm.m.diag[i + 0][jj] = (i + 0 < jj) ? r.x : 0.0f;
                sm.m.diag[i + 1][jj] = (i + 1 < jj) ? r.y : 0.0f;
                sm.m.diag[i + 2][jj] = (i + 2 < jj) ? r.z : 0.0f;
                sm.m.diag[i + 3][jj] = (i + 3 < jj) ? r.w : 0.0f;
            }
        }
        __syncthreads();

        // ======= in-panel sequential micro-solve: thread b owns a sample =====
        if (tid < BT) {
            float ul[PP];
            const float* zp = z + (size_t)(b0 + tid) * K_DIM + j0;
            #pragma unroll
            for (int q = 0; q < 16; ++q) {
                const float4 zq = *(const float4*)(zp + 4 * q);
                const float4 aq = *(const float4*)&sm.m.up[tid][4 * q];
                ul[4*q+0] = aq.x + zq.x;
                ul[4*q+1] = aq.y + zq.y;
                ul[4*q+2] = aq.z + zq.z;
                ul[4*q+3] = aq.w + zq.w;
            }
            const int jrel = t_abs - j0;
            // column sweep; masked diag lets each step start at a 4-aligned block
            #pragma unroll
            for (int i = 0; i < PP; ++i) {
                const float val = (jrel == i) ? vint : ul[i];
                ul[i] = val;
                #pragma unroll
                for (int q = (i >> 2); q < 16; ++q) {
                    const float4 d = *(const float4*)&sm.m.diag[i][4 * q];
                    ul[4*q+0] = fmaf(d.x, val, ul[4*q+0]);
                    ul[4*q+1] = fmaf(d.y, val, ul[4*q+1]);
                    ul[4*q+2] = fmaf(d.z, val, ul[4*q+2]);
                    ul[4*q+3] = fmaf(d.w, val, ul[4*q+3]);
                }
            }
            #pragma unroll
            for (int q = 0; q < 16; ++q) {
                float4 v;
                v.x = ul[4*q+0]; v.y = ul[4*q+1]; v.z = ul[4*q+2]; v.w = ul[4*q+3];
                *(float4*)&sm.m.up[tid][4 * q] = v;
            }
        }
        __syncthreads();

        // ---- coalesced panel writeout (out doubles as u-scratch) ----
        {
            const int r0 = tid >> 4;          // 0..15
            const int c0 = (tid & 15) * 4;    // 0..60
            #pragma unroll
            for (int pass = 0; pass < 4; ++pass) {
                const int row = pass * 16 + r0;
                const float4 v = *(const float4*)&sm.m.up[row][c0];
                *(float4*)(out + (size_t)(b0 + row) * K_DIM + j0 + c0) = v;
            }
        }
        __syncthreads();   // global writes + smem reuse ordered before next panel
    }
}

extern "C" void kernel_launch(void* const* d_in, const int* in_sizes, int n_in,
                              void* d_out, int out_size) {
    const float* z     = (const float*)d_in[0];
    const int*   tgt   = (const int*)  d_in[1];
    const int*   vari  = (const int*)  d_in[2];
    const float* A     = (const float*)d_in[3];
    const float* means = (const float*)d_in[4];
    const float* logsc = (const float*)d_in[5];
    float* out = (float*)d_out;
    (void)in_sizes; (void)n_in; (void)out_size;

    scm_kernel<<<B_SZ / BT, NTH>>>(z, tgt, vari, A, means, logsc, out);
}